// round 16
// baseline (speedup 1.0000x reference)
#include <cuda_runtime.h>
#include <math_constants.h>
#include <cstdint>

// KNN_18614388261211 — farthest-(k+1) selection, drop rank 0.
// x: (8,2048,3) f32 -> BN=16384 points, k=16.
// out: [ dists (BN*16 f32 = pair values) | idx (BN*16 as f32) ]
//
// R13 = R12 (201us) with FFMA2-packed hot loop:
//   - both candidates of a pair live in one f32x2 register; per row the filter
//     is 3 fma.rn.f32x2 + 1 add.rn.f32x2 (ptxas never emits FFMA2 on its own)
//   - qualification = sign test on d = m - sqj (superset logic unchanged)
//   - packed per-row d2 kept in regs; slow path ballots on its sign bits
//   - NW=27 (864 thr) for the 75-reg budget; exact insert path bit-identical

#define BN       16384
#define KOUT     16
#define R        4                 // rows per warp-task
#define NW       27                // warps per block (864 thr -> 75-reg cap)
#define NTHREADS (NW * 32)
#define NBLOCKS  152
#define NTASKS   (BN / R)          // 4096 warp-tasks (152*27 = 4104 slots)
#define NITER2   (BN / 64)         // 256 candidate groups of 64
#define SMEM_BYTES (BN * 3 * 4)    // 192 KB: float2 xy[BN] + float z[BN]
#define SLACK    1e-3f             // conservative filter slack (>> packed-math error)

typedef unsigned long long ull;

__device__ __forceinline__ float fneg(float v) {
    return __int_as_float(__float_as_int(v) ^ 0x80000000u);
}
__device__ __forceinline__ ull pack2(float lo, float hi) {
    ull r; asm("mov.b64 %0,{%1,%2};" : "=l"(r) : "f"(lo), "f"(hi)); return r;
}
__device__ __forceinline__ float lo32f(ull v) {
    float a, b; asm("mov.b64 {%0,%1},%2;" : "=f"(a), "=f"(b) : "l"(v)); return a;
}
__device__ __forceinline__ ull f2fma(ull a, ull b, ull c) {
    ull r; asm("fma.rn.f32x2 %0,%1,%2,%3;" : "=l"(r) : "l"(a), "l"(b), "l"(c)); return r;
}
__device__ __forceinline__ ull f2mul(ull a, ull b) {
    ull r; asm("mul.rn.f32x2 %0,%1,%2;" : "=l"(r) : "l"(a), "l"(b)); return r;
}
__device__ __forceinline__ ull f2add(ull a, ull b) {
    ull r; asm("add.rn.f32x2 %0,%1,%2;" : "=l"(r) : "l"(a), "l"(b)); return r;
}
#define LOSIGN(v) ((int)(unsigned)(v))
#define HISIGN(v) ((int)((v) >> 32))

// Slow path for one candidate; quals come from sign bits of packed d2[r]
// (SIGNF selects lo=cand A / hi=cand B). Exact comparator as in R8/R10.
#define PROCESS_CAND(QX, QY, QZ, SIGNF, NJBASE)                                 \
    do {                                                                        \
        const float nsqj_ = fneg(__fadd_rn(__fadd_rn(__fmul_rn((QX), (QX)),     \
                                                     __fmul_rn((QY), (QY))),    \
                                           __fmul_rn((QZ), (QZ))));             \
        _Pragma("unroll")                                                       \
        for (int r_ = 0; r_ < R; r_++) {                                        \
            unsigned b_ = __ballot_sync(FULL, SIGNF(d2[r_]) < 0);               \
            if (!b_) continue;                                                  \
            const float px2_ = lo32f(pxd[r_]);                                  \
            const float py2_ = lo32f(pyd[r_]);                                  \
            const float pz2_ = lo32f(pzd[r_]);                                  \
            const float dot2x_ = __fadd_rn(__fadd_rn(__fmul_rn(px2_, (QX)),     \
                                                     __fmul_rn(py2_, (QY))),    \
                                           __fmul_rn(pz2_, (QZ)));              \
            const float pv_ = __fadd_rn(__fadd_rn(dot2x_, nsqi[r_]), nsqj_);    \
            bool inserted_ = false;                                             \
            while (b_) {                                                        \
                const int src_ = __ffs(b_) - 1;                                 \
                b_ &= b_ - 1;                                                   \
                const float nv_ = __shfl_sync(FULL, pv_, src_);                 \
                const int   nj_ = (NJBASE) + 2 * src_;                          \
                const bool after_ = (lane <= 16) &&                             \
                    ((lv[r_] > nv_) || (lv[r_] == nv_ && lj[r_] > nj_));        \
                const unsigned im_ = __ballot_sync(FULL, after_) & 0x1ffffu;    \
                const float upv_ = __shfl_up_sync(FULL, lv[r_], 1);             \
                const int   upj_ = __shfl_up_sync(FULL, lj[r_], 1);             \
                if (im_) {                                                      \
                    const int pos_ = __ffs(im_) - 1;                            \
                    if (lane <= 16) {                                           \
                        if (lane > pos_)       { lv[r_] = upv_; lj[r_] = upj_; }\
                        else if (lane == pos_) { lv[r_] = nv_;  lj[r_] = nj_;  }\
                    }                                                           \
                    inserted_ = true;                                           \
                }                                                               \
            }                                                                   \
            if (inserted_) {                                                    \
                const float nt_ = __shfl_sync(FULL, lv[r_], 16);                \
                const float c_ = __fsub_rn(__fadd_rn(nsqi[r_], fneg(nt_)), SLACK); \
                cRd[r_] = pack2(c_, c_);                                        \
            }                                                                   \
        }                                                                       \
    } while (0)

__global__ __launch_bounds__(NTHREADS, 1)
void knn_kernel(const float* __restrict__ x, float* __restrict__ out) {
    extern __shared__ float smem[];
    float2* __restrict__ sxy = reinterpret_cast<float2*>(smem);  // [BN]
    float*  __restrict__ sz  = smem + 2 * BN;                    // [BN]

    for (int p = threadIdx.x; p < BN; p += NTHREADS) {
        sxy[p] = make_float2(x[3 * p + 0], x[3 * p + 1]);
        sz[p]  = x[3 * p + 2];
    }
    __syncthreads();

    const int lane = threadIdx.x & 31;
    const int warp = threadIdx.x >> 5;
    const int gw   = blockIdx.x * NW + warp;     // global warp-task id
    if (gw >= NTASKS) return;                    // warp-uniform; after the sync
    const int row0 = gw * R;
    const unsigned FULL = 0xffffffffu;

    // Packed per-row constants (dup f32x2) + scalar state; compile-time indexed.
    ull  pxd[R], pyd[R], pzd[R], cRd[R], d2[R];
    float nsqi[R], lv[R];
    int   lj[R];

#pragma unroll
    for (int r = 0; r < R; r++) {
        const float2 pxy = sxy[row0 + r];
        const float  pz  = sz[row0 + r];
        const float sqi = __fadd_rn(__fadd_rn(__fmul_rn(pxy.x, pxy.x),
                                              __fmul_rn(pxy.y, pxy.y)),
                                    __fmul_rn(pz, pz));
        const float px2 = __fadd_rn(pxy.x, pxy.x);   // exact doubling
        const float py2 = __fadd_rn(pxy.y, pxy.y);
        const float pz2 = __fadd_rn(pz, pz);
        pxd[r] = pack2(px2, px2);
        pyd[r] = pack2(py2, py2);
        pzd[r] = pack2(pz2, pz2);
        nsqi[r] = fneg(sqi);
    }

    // ---- Bootstrap: sort candidates 0..63 per row, seed list with ranks 0..16.
    {
        const float4 xy = *reinterpret_cast<const float4*>(sxy + (lane << 1));
        const float2 zz = *reinterpret_cast<const float2*>(sz + (lane << 1));
        const float nsq0 = fneg(__fadd_rn(__fadd_rn(__fmul_rn(xy.x, xy.x),
                                                    __fmul_rn(xy.y, xy.y)),
                                          __fmul_rn(zz.x, zz.x)));
        const float nsq1 = fneg(__fadd_rn(__fadd_rn(__fmul_rn(xy.z, xy.z),
                                                    __fmul_rn(xy.w, xy.w)),
                                          __fmul_rn(zz.y, zz.y)));
#pragma unroll
        for (int r = 0; r < R; r++) {
            const float px2 = lo32f(pxd[r]);
            const float py2 = lo32f(pyd[r]);
            const float pz2 = lo32f(pzd[r]);
            const float d0 = __fadd_rn(__fadd_rn(__fmul_rn(px2, xy.x),
                                                 __fmul_rn(py2, xy.y)),
                                       __fmul_rn(pz2, zz.x));
            const float d1 = __fadd_rn(__fadd_rn(__fmul_rn(px2, xy.z),
                                                 __fmul_rn(py2, xy.w)),
                                       __fmul_rn(pz2, zz.y));
            float pv0 = __fadd_rn(__fadd_rn(d0, nsqi[r]), nsq0);
            float pv1 = __fadd_rn(__fadd_rn(d1, nsqi[r]), nsq1);
            int   id0 = (lane << 1);
            int   id1 = (lane << 1) + 1;

            // 64-element bitonic sort, ascending lexicographic (pv, id).
#pragma unroll
            for (int k = 2; k <= 64; k <<= 1) {
#pragma unroll
                for (int j = k >> 1; j >= 1; j >>= 1) {
                    const bool asc = (k == 64) || ((lane & (k >> 1)) == 0);
                    if (j >= 2) {
                        const int L = j >> 1;
                        const float opv0 = __shfl_xor_sync(FULL, pv0, L);
                        const float opv1 = __shfl_xor_sync(FULL, pv1, L);
                        const int   oid0 = __shfl_xor_sync(FULL, id0, L);
                        const int   oid1 = __shfl_xor_sync(FULL, id1, L);
                        const bool lower = (lane & L) == 0;
                        const bool keepmin = (asc == lower);
                        const bool l0 = (opv0 < pv0) || (opv0 == pv0 && oid0 < id0);
                        const bool l1 = (opv1 < pv1) || (opv1 == pv1 && oid1 < id1);
                        if (keepmin ? l0 : !l0) { pv0 = opv0; id0 = oid0; }
                        if (keepmin ? l1 : !l1) { pv1 = opv1; id1 = oid1; }
                    } else {
                        const bool less = (pv1 < pv0) || (pv1 == pv0 && id1 < id0);
                        if (asc ? less : !less) {
                            const float tp = pv0; pv0 = pv1; pv1 = tp;
                            const int   ti = id0; id0 = id1; id1 = ti;
                        }
                    }
                }
            }
            const float a0 = __shfl_sync(FULL, pv0, lane >> 1);
            const float a1 = __shfl_sync(FULL, pv1, lane >> 1);
            const int   b0 = __shfl_sync(FULL, id0, lane >> 1);
            const int   b1 = __shfl_sync(FULL, id1, lane >> 1);
            lv[r] = (lane <= 16) ? ((lane & 1) ? a1 : a0) : CUDART_INF_F;
            lj[r] = (lane <= 16) ? ((lane & 1) ? b1 : b0) : 0x7fffffff;
            const float nt = __shfl_sync(FULL, lv[r], 16);
            const float c = __fsub_rn(__fadd_rn(nsqi[r], fneg(nt)), SLACK);
            cRd[r] = pack2(c, c);
        }
    }

    // ---- Main loop, candidates packed 2-wide in f32x2 (A=lo, B=hi).
    for (int t = 1; t < NITER2; t++) {
        const int j0 = (t << 6) + (lane << 1);
        const float4 xy = *reinterpret_cast<const float4*>(sxy + j0); // LDS.128
        const float2 zz = *reinterpret_cast<const float2*>(sz + j0);  // LDS.64

        const ull qx2 = pack2(xy.x, xy.z);
        const ull qy2 = pack2(xy.y, xy.w);
        const ull qz2 = pack2(zz.x, zz.y);
        // packed sqj (filter only), then negate both halves (exact sign flip)
        const ull sq2  = f2fma(qx2, qx2, f2fma(qy2, qy2, f2mul(qz2, qz2)));
        const ull nsq2 = sq2 ^ 0x8000000080000000ULL;

        // d2[r] = (2*dot_r + (-sqi_r - T_r - SLACK)) - sqj, both candidates.
        ull dAll = 0;
#pragma unroll
        for (int r = 0; r < R; r++) {
            const ull m2 = f2fma(pzd[r], qz2,
                           f2fma(pyd[r], qy2,
                           f2fma(pxd[r], qx2, cRd[r])));
            d2[r] = f2add(m2, nsq2);
            dAll = (r == 0) ? d2[0] : (dAll | d2[r]);  // sign(or)=or(signs)
        }

        const bool qA = LOSIGN(dAll) < 0;
        const bool qB = HISIGN(dAll) < 0;
        if (__any_sync(FULL, qA || qB)) {
            const unsigned gA = __ballot_sync(FULL, qA);
            const unsigned gB = __ballot_sync(FULL, qB);
            const int njbase = t << 6;
            if (gA) PROCESS_CAND(xy.x, xy.y, zz.x, LOSIGN, njbase);
            if (gB) PROCESS_CAND(xy.z, xy.w, zz.y, HISIGN, njbase + 1);
        }
    }

    // Ranks 1..16 are the output (rank 0 dropped by the reference).
#pragma unroll
    for (int r = 0; r < R; r++) {
        if (lane >= 1 && lane <= 16) {
            const int row = row0 + r;
            out[(size_t)row * KOUT + (lane - 1)] = lv[r];
            out[(size_t)BN * KOUT + (size_t)row * KOUT + (lane - 1)] = (float)lj[r];
        }
    }
}

extern "C" void kernel_launch(void* const* d_in, const int* in_sizes, int n_in,
                              void* d_out, int out_size) {
    const float* x = (const float*)d_in[0];
    float* out = (float*)d_out;
    cudaFuncSetAttribute(knn_kernel, cudaFuncAttributeMaxDynamicSharedMemorySize,
                         SMEM_BYTES);
    knn_kernel<<<NBLOCKS, NTHREADS, SMEM_BYTES>>>(x, out);
}

// round 17
// speedup vs baseline: 2.7016x; 2.7016x over previous
#include <cuda_runtime.h>
#include <math_constants.h>
#include <cstdint>

// KNN_18614388261211 — farthest-(k+1) selection, drop rank 0.
// x: (8,2048,3) f32 -> BN=16384 points, k=16.
// out: [ dists (BN*16 f32 = pair values) | idx (BN*16 as f32) ]
//
// R16: radius-ordered scan + exact early exit (triangle inequality).
//   kernel A: bucket-sort points by descending r^2 (256 buckets) into device
//             scratch + per-group suffix-max radius g_rup[].
//   kernel B: R12 selection logic (bit-identical comparator/filter) over the
//             sorted stream; warp breaks when g_rup[t] < min_r(sqrt(D_r)-|p_r|-eps).
//   Candidate visit order changes but min-17 under strict (pv,idx) order is
//   order-independent -> identical output.

#define BN       16384
#define KOUT     16
#define R        4
#define NW       27                 // 864 thr -> 75-reg cap
#define NTHREADS (NW * 32)
#define NBLOCKS  152
#define NTASKS   (BN / R)           // 4096 warp-tasks (152*27 = 4104 slots)
#define NGROUPS  (BN / 64)          // 256
#define SLACK    1e-3f
#define NEED_MARGIN 1e-2f           // early-exit safety margin (>> fp error)
#define R2SCALE  8.0f               // bucket = min(255, floor(r2*8))

// smem layout (bytes): sxy 131072 | sz 65536 | soid 32768 | srup 1024
#define SM_SZ_OFF   131072
#define SM_OID_OFF  196608
#define SM_RUP_OFF  229376
#define SMEM_BYTES  230400

__device__ float2         g_sxy[BN];
__device__ float          g_sz[BN];
__device__ unsigned short g_oid[BN];
__device__ float          g_rup[NGROUPS];

__device__ __forceinline__ float fneg(float v) {
    return __int_as_float(__float_as_int(v) ^ 0x80000000u);
}

// ---------------- kernel A: bucket sort by descending r^2 ----------------
__global__ __launch_bounds__(1024, 1)
void sort_kernel(const float* __restrict__ x) {
    __shared__ int hist[256];
    __shared__ int base[256];
    __shared__ int gmax_i[NGROUPS];   // per-group max r2 (float bits, r2>=0)
    const int tid = threadIdx.x;
    for (int i = tid; i < 256; i += 1024) hist[i] = 0;
    for (int i = tid; i < NGROUPS; i += 1024) gmax_i[i] = 0;
    __syncthreads();
    for (int p = tid; p < BN; p += 1024) {
        const float a = x[3*p], b = x[3*p+1], c = x[3*p+2];
        const float r2 = __fmaf_rn(a, a, __fmaf_rn(b, b, __fmul_rn(c, c)));
        const int k = min(255, (int)(r2 * R2SCALE));
        atomicAdd(&hist[255 - k], 1);
    }
    __syncthreads();
    if (tid == 0) { int s = 0; for (int i = 0; i < 256; i++) { base[i] = s; s += hist[i]; } }
    __syncthreads();
    for (int p = tid; p < BN; p += 1024) {
        const float a = x[3*p], b = x[3*p+1], c = x[3*p+2];
        const float r2 = __fmaf_rn(a, a, __fmaf_rn(b, b, __fmul_rn(c, c)));
        const int k = min(255, (int)(r2 * R2SCALE));
        const int pos = atomicAdd(&base[255 - k], 1);
        g_sxy[pos] = make_float2(a, b);
        g_sz[pos]  = c;
        g_oid[pos] = (unsigned short)p;
        atomicMax(&gmax_i[pos >> 6], __float_as_int(r2));
    }
    __syncthreads();
    if (tid == 0) {
        float suf = 0.f;
        for (int g = NGROUPS - 1; g >= 0; g--) {
            suf = fmaxf(suf, __int_as_float(gmax_i[g]));
            g_rup[g] = sqrtf(suf) + 1e-3f;   // conservative max radius in suffix
        }
    }
}

// Slow path for one candidate; MARR = hot-loop filter values, OIDV = lane's
// original index for this candidate. Exact comparator (bit-identical to R12).
#define PROCESS_CAND(QX, QY, QZ, MARR, SQJF, OIDV)                              \
    do {                                                                        \
        const float nsqj_ = fneg(__fadd_rn(__fadd_rn(__fmul_rn((QX), (QX)),     \
                                                     __fmul_rn((QY), (QY))),    \
                                           __fmul_rn((QZ), (QZ))));             \
        _Pragma("unroll")                                                       \
        for (int r_ = 0; r_ < R; r_++) {                                        \
            unsigned b_ = __ballot_sync(FULL, MARR[r_] < (SQJF));               \
            if (!b_) continue;                                                  \
            const float dot2x_ = __fadd_rn(__fadd_rn(__fmul_rn(px2[r_], (QX)),  \
                                                     __fmul_rn(py2[r_], (QY))), \
                                           __fmul_rn(pz2[r_], (QZ)));           \
            const float pv_ = __fadd_rn(__fadd_rn(dot2x_, nsqi[r_]), nsqj_);    \
            bool inserted_ = false;                                             \
            while (b_) {                                                        \
                const int src_ = __ffs(b_) - 1;                                 \
                b_ &= b_ - 1;                                                   \
                const float nv_ = __shfl_sync(FULL, pv_, src_);                 \
                const int   nj_ = __shfl_sync(FULL, (OIDV), src_);              \
                const bool after_ = (lane <= 16) &&                             \
                    ((lv[r_] > nv_) || (lv[r_] == nv_ && lj[r_] > nj_));        \
                const unsigned im_ = __ballot_sync(FULL, after_) & 0x1ffffu;    \
                const float upv_ = __shfl_up_sync(FULL, lv[r_], 1);             \
                const int   upj_ = __shfl_up_sync(FULL, lj[r_], 1);             \
                if (im_) {                                                      \
                    const int pos_ = __ffs(im_) - 1;                            \
                    if (lane <= 16) {                                           \
                        if (lane > pos_)       { lv[r_] = upv_; lj[r_] = upj_; }\
                        else if (lane == pos_) { lv[r_] = nv_;  lj[r_] = nj_;  }\
                    }                                                           \
                    inserted_ = true;                                           \
                }                                                               \
            }                                                                   \
            if (inserted_) {                                                    \
                const float nt_ = __shfl_sync(FULL, lv[r_], 16);                \
                cR[r_] = __fsub_rn(__fadd_rn(nsqi[r_], fneg(nt_)), SLACK);      \
            }                                                                   \
        }                                                                       \
    } while (0)

#define RECOMPUTE_MINNEED()                                                     \
    do {                                                                        \
        minNeed = CUDART_INF_F;                                                 \
        _Pragma("unroll")                                                       \
        for (int rr = 0; rr < R; rr++) {                                        \
            const float nt__ = __shfl_sync(FULL, lv[rr], 16);                   \
            const float need__ = sqrtf(fmaxf(-nt__, 0.f))                       \
                                 - sqrtf(-nsqi[rr]) - NEED_MARGIN;              \
            minNeed = fminf(minNeed, need__);                                   \
        }                                                                       \
    } while (0)

// ---------------- kernel B: selection over sorted stream ----------------
__global__ __launch_bounds__(NTHREADS, 1)
void knn_kernel(const float* __restrict__ x, float* __restrict__ out) {
    extern __shared__ char smemraw[];
    float2*         sxy  = reinterpret_cast<float2*>(smemraw);
    float*          sz   = reinterpret_cast<float*>(smemraw + SM_SZ_OFF);
    unsigned short* soid = reinterpret_cast<unsigned short*>(smemraw + SM_OID_OFF);
    float*          srup = reinterpret_cast<float*>(smemraw + SM_RUP_OFF);

    for (int i = threadIdx.x; i < BN; i += NTHREADS) {
        sxy[i]  = g_sxy[i];
        sz[i]   = g_sz[i];
        soid[i] = g_oid[i];
    }
    for (int i = threadIdx.x; i < NGROUPS; i += NTHREADS) srup[i] = g_rup[i];
    __syncthreads();

    const int lane = threadIdx.x & 31;
    const int warp = threadIdx.x >> 5;
    const int gw   = blockIdx.x * NW + warp;
    if (gw >= NTASKS) return;                  // warp-uniform; after the sync
    const int row0 = gw * R;
    const unsigned FULL = 0xffffffffu;

    float px2[R], py2[R], pz2[R], nsqi[R], cR[R], lv[R];
    int   lj[R];

#pragma unroll
    for (int r = 0; r < R; r++) {
        // row coords from ORIGINAL (unsorted) input
        const float px = x[3*(row0+r)], py = x[3*(row0+r)+1], pz = x[3*(row0+r)+2];
        const float sqi = __fadd_rn(__fadd_rn(__fmul_rn(px, px), __fmul_rn(py, py)),
                                    __fmul_rn(pz, pz));
        px2[r] = __fadd_rn(px, px);
        py2[r] = __fadd_rn(py, py);
        pz2[r] = __fadd_rn(pz, pz);
        nsqi[r] = fneg(sqi);
    }

    // ---- Bootstrap: sorted group 0 = 64 highest-radius points.
    {
        const float4 xy = *reinterpret_cast<const float4*>(sxy + (lane << 1));
        const float2 zz = *reinterpret_cast<const float2*>(sz + (lane << 1));
        const unsigned op = *reinterpret_cast<const unsigned*>(soid + (lane << 1));
        const float nsq0 = fneg(__fadd_rn(__fadd_rn(__fmul_rn(xy.x, xy.x),
                                                    __fmul_rn(xy.y, xy.y)),
                                          __fmul_rn(zz.x, zz.x)));
        const float nsq1 = fneg(__fadd_rn(__fadd_rn(__fmul_rn(xy.z, xy.z),
                                                    __fmul_rn(xy.w, xy.w)),
                                          __fmul_rn(zz.y, zz.y)));
#pragma unroll
        for (int r = 0; r < R; r++) {
            const float d0 = __fadd_rn(__fadd_rn(__fmul_rn(px2[r], xy.x),
                                                 __fmul_rn(py2[r], xy.y)),
                                       __fmul_rn(pz2[r], zz.x));
            const float d1 = __fadd_rn(__fadd_rn(__fmul_rn(px2[r], xy.z),
                                                 __fmul_rn(py2[r], xy.w)),
                                       __fmul_rn(pz2[r], zz.y));
            float pv0 = __fadd_rn(__fadd_rn(d0, nsqi[r]), nsq0);
            float pv1 = __fadd_rn(__fadd_rn(d1, nsqi[r]), nsq1);
            int   id0 = (int)(op & 0xffffu);
            int   id1 = (int)(op >> 16);

#pragma unroll
            for (int k = 2; k <= 64; k <<= 1) {
#pragma unroll
                for (int j = k >> 1; j >= 1; j >>= 1) {
                    const bool asc = (k == 64) || ((lane & (k >> 1)) == 0);
                    if (j >= 2) {
                        const int L = j >> 1;
                        const float opv0 = __shfl_xor_sync(FULL, pv0, L);
                        const float opv1 = __shfl_xor_sync(FULL, pv1, L);
                        const int   oid0 = __shfl_xor_sync(FULL, id0, L);
                        const int   oid1 = __shfl_xor_sync(FULL, id1, L);
                        const bool lower = (lane & L) == 0;
                        const bool keepmin = (asc == lower);
                        const bool l0 = (opv0 < pv0) || (opv0 == pv0 && oid0 < id0);
                        const bool l1 = (opv1 < pv1) || (opv1 == pv1 && oid1 < id1);
                        if (keepmin ? l0 : !l0) { pv0 = opv0; id0 = oid0; }
                        if (keepmin ? l1 : !l1) { pv1 = opv1; id1 = oid1; }
                    } else {
                        const bool less = (pv1 < pv0) || (pv1 == pv0 && id1 < id0);
                        if (asc ? less : !less) {
                            const float tp = pv0; pv0 = pv1; pv1 = tp;
                            const int   ti = id0; id0 = id1; id1 = ti;
                        }
                    }
                }
            }
            const float a0 = __shfl_sync(FULL, pv0, lane >> 1);
            const float a1 = __shfl_sync(FULL, pv1, lane >> 1);
            const int   b0 = __shfl_sync(FULL, id0, lane >> 1);
            const int   b1 = __shfl_sync(FULL, id1, lane >> 1);
            lv[r] = (lane <= 16) ? ((lane & 1) ? a1 : a0) : CUDART_INF_F;
            lj[r] = (lane <= 16) ? ((lane & 1) ? b1 : b0) : 0x7fffffff;
            const float nt = __shfl_sync(FULL, lv[r], 16);
            cR[r] = __fsub_rn(__fadd_rn(nsqi[r], fneg(nt)), SLACK);
        }
    }

    float minNeed;
    RECOMPUTE_MINNEED();

    // ---- Main scan over sorted groups with exact early exit.
    for (int t = 1; t < NGROUPS; t++) {
        if (srup[t] < minNeed) break;          // no remaining point can qualify

        const int j0 = (t << 6) + (lane << 1);
        const float4 xy = *reinterpret_cast<const float4*>(sxy + j0);
        const float2 zz = *reinterpret_cast<const float2*>(sz + j0);

        const float sqA = __fmaf_rn(xy.x, xy.x,
                          __fmaf_rn(xy.y, xy.y, __fmul_rn(zz.x, zz.x)));
        const float sqB = __fmaf_rn(xy.z, xy.z,
                          __fmaf_rn(xy.w, xy.w, __fmul_rn(zz.y, zz.y)));

        float mA[R], mB[R];
        float mnA = CUDART_INF_F, mnB = CUDART_INF_F;
#pragma unroll
        for (int r = 0; r < R; r++) {
            mA[r] = __fmaf_rn(pz2[r], zz.x,
                    __fmaf_rn(py2[r], xy.y,
                    __fmaf_rn(px2[r], xy.x, cR[r])));
            mB[r] = __fmaf_rn(pz2[r], zz.y,
                    __fmaf_rn(py2[r], xy.w,
                    __fmaf_rn(px2[r], xy.z, cR[r])));
            mnA = fminf(mnA, mA[r]);
            mnB = fminf(mnB, mB[r]);
        }

        const bool qA = mnA < sqA;
        const bool qB = mnB < sqB;
        if (__any_sync(FULL, qA || qB)) {
            const unsigned gA = __ballot_sync(FULL, qA);
            const unsigned gB = __ballot_sync(FULL, qB);
            const unsigned op = *reinterpret_cast<const unsigned*>(soid + j0);
            const int oidA = (int)(op & 0xffffu);
            const int oidB = (int)(op >> 16);
            if (gA) PROCESS_CAND(xy.x, xy.y, zz.x, mA, sqA, oidA);
            if (gB) PROCESS_CAND(xy.z, xy.w, zz.y, mB, sqB, oidB);
            RECOMPUTE_MINNEED();
        }
    }

    // Ranks 1..16 are the output (rank 0 dropped by the reference).
#pragma unroll
    for (int r = 0; r < R; r++) {
        if (lane >= 1 && lane <= 16) {
            const int row = row0 + r;
            out[(size_t)row * KOUT + (lane - 1)] = lv[r];
            out[(size_t)BN * KOUT + (size_t)row * KOUT + (lane - 1)] = (float)lj[r];
        }
    }
}

extern "C" void kernel_launch(void* const* d_in, const int* in_sizes, int n_in,
                              void* d_out, int out_size) {
    const float* x = (const float*)d_in[0];
    float* out = (float*)d_out;
    cudaFuncSetAttribute(knn_kernel, cudaFuncAttributeMaxDynamicSharedMemorySize,
                         SMEM_BYTES);
    sort_kernel<<<1, 1024>>>(x);
    knn_kernel<<<NBLOCKS, NTHREADS, SMEM_BYTES>>>(x, out);
}